// round 2
// baseline (speedup 1.0000x reference)
#include <cuda_runtime.h>

#define C_CHUNKS 16
#define NCW      2048
#define SUB      64
#define DIM      1024
#define TM       128
#define TN       128

typedef unsigned long long ull;

// scratch: per-codeword squared norms (16*2048 floats = 128KB)
__device__ float g_cbsq[C_CHUNKS * NCW];

// packed f32x2 fma: d.lo = a.lo*b.lo + c.lo ; d.hi = a.hi*b.hi + c.hi
__device__ __forceinline__ ull fma2(ull a, ull b, ull c) {
    ull d;
    asm("fma.rn.f32x2 %0, %1, %2, %3;" : "=l"(d) : "l"(a), "l"(b), "l"(c));
    return d;
}
__device__ __forceinline__ ull dup2(float v) {
    ull d;
    asm("mov.b64 %0, {%1, %1};" : "=l"(d) : "f"(v));
    return d;
}
__device__ __forceinline__ void unpack2(ull v, float& lo, float& hi) {
    asm("mov.b64 {%0, %1}, %2;" : "=f"(lo), "=f"(hi) : "l"(v));
}

// ---------------------------------------------------------------------------
// Kernel 0: codeword squared norms. One warp per codeword, coalesced float2.
// ---------------------------------------------------------------------------
__global__ void cbsq_kernel(const float* __restrict__ cb) {
    int w = (blockIdx.x * blockDim.x + threadIdx.x) >> 5;
    int lane = threadIdx.x & 31;
    if (w >= C_CHUNKS * NCW) return;
    const float2* p = reinterpret_cast<const float2*>(cb + (size_t)w * SUB);
    float2 v = p[lane];
    float s = v.x * v.x + v.y * v.y;
    #pragma unroll
    for (int o = 16; o > 0; o >>= 1) s += __shfl_xor_sync(0xffffffffu, s, o);
    if (lane == 0) g_cbsq[w] = s;
}

// ---------------------------------------------------------------------------
// Kernel 1: fused dots-GEMM + argmin + gather, packed f32x2 mainloop.
// Accumulators pack adjacent codeword columns (j, j+1) into one f32x2 pair;
// B pairs come packed for free from the float4/ulonglong2 LDS, A is
// half-duplicated on the (idle) ALU pipe. Exact fp32 arithmetic per lane.
// ---------------------------------------------------------------------------
__global__ __launch_bounds__(256, 2)
void vq_kernel(const float* __restrict__ x, const float* __restrict__ cb,
               float* __restrict__ out) {
    extern __shared__ float sm[];
    float* sA   = sm;                      // [SUB][TM]  x tile, k-major
    float* sB   = sm + SUB * TM;           // [SUB][TN]  codeword tile, k-major, permuted cols
    float* sXsq = sm + 2 * SUB * TM;       // [TM]
    int*   sIdx = reinterpret_cast<int*>(sm + 2 * SUB * TM + TM);  // [TM]

    const int tid   = threadIdx.x;
    const int chunk = blockIdx.y;
    const int t0    = blockIdx.x * TM;

    const float* cbc = cb + (size_t)chunk * NCW * SUB;
    const float* cqc = g_cbsq + chunk * NCW;

    // ---- load x tile transposed into sA, compute per-token |x|^2 ----
    {
        const int r = tid >> 1, h = tid & 1;
        const float4* xp = reinterpret_cast<const float4*>(
            x + (size_t)(t0 + r) * DIM + chunk * SUB + h * 32);
        float ssq = 0.f;
        #pragma unroll
        for (int q = 0; q < 8; q++) {
            float4 v = xp[q];
            int k = h * 32 + q * 4;
            sA[(k + 0) * TM + r] = v.x;
            sA[(k + 1) * TM + r] = v.y;
            sA[(k + 2) * TM + r] = v.z;
            sA[(k + 3) * TM + r] = v.w;
            ssq += v.x * v.x;
            ssq += v.y * v.y;
            ssq += v.z * v.z;
            ssq += v.w * v.w;
        }
        ssq += __shfl_xor_sync(0xffffffffu, ssq, 1);
        if (h == 0) sXsq[r] = ssq;
    }
    __syncthreads();

    const int ty = tid >> 4, tx = tid & 15;

    // hoist the 8 xsq values this thread needs
    float xq[8];
    #pragma unroll
    for (int i = 0; i < 8; i++) xq[i] = sXsq[ty * 8 + i];

    float minv[8];
    int   mini[8];
    #pragma unroll
    for (int i = 0; i < 8; i++) { minv[i] = 3.4028235e38f; mini[i] = 0; }

    for (int n0 = 0; n0 < NCW; n0 += TN) {
        __syncthreads();   // protect sB reuse from previous iteration's readers
        {
            // Store codeword r's k-values at permuted column m so that the
            // inner-loop 16B reads (tx*4 and 64+tx*4) are conflict-free.
            // Inverse map: column tx*4+q      <-> codeword n0 + tx*8 + q
            //              column 64+tx*4+q   <-> codeword n0 + tx*8 + 4 + q
            const int r = tid >> 1, h = tid & 1;
            const int m = ((r & 4) << 4) | ((r >> 3) << 2) | (r & 3);
            const float4* cp = reinterpret_cast<const float4*>(
                cbc + (size_t)(n0 + r) * SUB + h * 32);
            #pragma unroll
            for (int q = 0; q < 8; q++) {
                float4 v = cp[q];
                int k = h * 32 + q * 4;
                sB[(k + 0) * TN + m] = v.x;
                sB[(k + 1) * TN + m] = v.y;
                sB[(k + 2) * TN + m] = v.z;
                sB[(k + 3) * TN + m] = v.w;
            }
        }
        __syncthreads();

        // acc2[i][p] packs (j=2p, j=2p+1) for row i
        ull acc2[8][4];
        #pragma unroll
        for (int i = 0; i < 8; i++)
            #pragma unroll
            for (int p = 0; p < 4; p++) acc2[i][p] = 0ull;

        #pragma unroll 4
        for (int k = 0; k < SUB; k++) {
            float4 a0 = *reinterpret_cast<const float4*>(&sA[k * TM + ty * 8]);
            float4 a1 = *reinterpret_cast<const float4*>(&sA[k * TM + ty * 8 + 4]);
            ulonglong2 b0 = *reinterpret_cast<const ulonglong2*>(&sB[k * TN + tx * 4]);
            ulonglong2 b1 = *reinterpret_cast<const ulonglong2*>(&sB[k * TN + 64 + tx * 4]);
            ull rb2[4] = {b0.x, b0.y, b1.x, b1.y};
            ull ra2[8];
            ra2[0] = dup2(a0.x); ra2[1] = dup2(a0.y);
            ra2[2] = dup2(a0.z); ra2[3] = dup2(a0.w);
            ra2[4] = dup2(a1.x); ra2[5] = dup2(a1.y);
            ra2[6] = dup2(a1.z); ra2[7] = dup2(a1.w);
            #pragma unroll
            for (int i = 0; i < 8; i++)
                #pragma unroll
                for (int p = 0; p < 4; p++)
                    acc2[i][p] = fma2(ra2[i], rb2[p], acc2[i][p]);
        }

        // d2 = xsq - 2*dot + cbsq ; running argmin (n ascending, strict <)
        #pragma unroll
        for (int p = 0; p < 4; p++) {
            int n = n0 + tx * 8 + 2 * p;
            float cq0 = __ldg(&cqc[n]);
            float cq1 = __ldg(&cqc[n + 1]);
            #pragma unroll
            for (int i = 0; i < 8; i++) {
                float d0, d1;
                unpack2(acc2[i][p], d0, d1);
                float d20 = fmaf(-2.f, d0, xq[i]) + cq0;
                float d21 = fmaf(-2.f, d1, xq[i]) + cq1;
                if (d20 < minv[i]) { minv[i] = d20; mini[i] = n; }
                if (d21 < minv[i]) { minv[i] = d21; mini[i] = n + 1; }
            }
        }
    }

    // ---- cross-thread argmin reduction (overlay on sB, padded stride 17) ----
    __syncthreads();
    float* redv = sB;
    int*   redi = reinterpret_cast<int*>(sB + TM * 17);
    #pragma unroll
    for (int i = 0; i < 8; i++) {
        int row = ty * 8 + i;
        redv[row * 17 + tx] = minv[i];
        redi[row * 17 + tx] = mini[i];
    }
    __syncthreads();
    if (tid < TM) {
        float bv = redv[tid * 17];
        int   bi = redi[tid * 17];
        #pragma unroll
        for (int t = 1; t < 16; t++) {
            float v  = redv[tid * 17 + t];
            int   ii = redi[tid * 17 + t];
            if (v < bv || (v == bv && ii < bi)) { bv = v; bi = ii; }
        }
        sIdx[tid] = bi;
    }
    __syncthreads();

    // ---- gather winning codewords straight to output (K == 1) ----
    {
        const int r = tid >> 1, h = tid & 1;
        const int idx = sIdx[r];
        const float4* src = reinterpret_cast<const float4*>(
            cbc + (size_t)idx * SUB + h * 32);
        float4* dst = reinterpret_cast<float4*>(
            out + (size_t)(t0 + r) * DIM + chunk * SUB + h * 32);
        #pragma unroll
        for (int q = 0; q < 8; q++) dst[q] = src[q];
    }
}

extern "C" void kernel_launch(void* const* d_in, const int* in_sizes, int n_in,
                              void* d_out, int out_size) {
    const float* x  = (const float*)d_in[0];   // (4, 2048, 1024) fp32
    const float* cb = (const float*)d_in[1];   // (16, 2048, 64) fp32
    float* out = (float*)d_out;

    const int tokens = in_sizes[0] / DIM;      // 8192

    // Kernel 0: codeword norms (one warp per codeword)
    int n_warps = C_CHUNKS * NCW;
    cbsq_kernel<<<(n_warps * 32 + 255) / 256, 256>>>(cb);

    // Kernel 1: fused search + gather
    size_t smem = (size_t)(2 * SUB * TM + TM) * sizeof(float) + TM * sizeof(int);
    cudaFuncSetAttribute(vq_kernel,
                         cudaFuncAttributeMaxDynamicSharedMemorySize, (int)smem);
    dim3 grid(tokens / TM, C_CHUNKS);
    vq_kernel<<<grid, 256, smem>>>(x, cb, out);
}